// round 6
// baseline (speedup 1.0000x reference)
#include <cuda_runtime.h>
#include <cuda_fp16.h>
#include <mma.h>

using namespace nvcuda;

#define NN 100000
#define NN_PAD 100096          // padded rows so wmma tile loads never run OOB
#define EE 1600000
#define DD 64
#define SCAN_B 1024
#define NB ((NN + SCAN_B - 1) / SCAN_B)   // 98

// ---------------- scratch (static __device__, zero-initialized) -------------
__device__ int    g_deg_out[NN];
__device__ int    g_deg_in[NN];
__device__ float  g_norm_src[NN];
__device__ float  g_norm_dst[NN];
__device__ int    g_row_ptr[NN + 1];
__device__ int    g_fill[NN];
__device__ int    g_col[EE];
__device__ int    g_bsum[NB];
__device__ __half g_xn[NN_PAD * DD];   // current layer input, pre-scaled by norm_src, fp16
__device__ __half g_A[NN_PAD * DD];    // aggregated features, fp16
__device__ float  g_bufA[NN * DD];
__device__ float  g_bufB[NN * DD];

// ---------------- degree histogram (deg arrays are zero on entry:
// static zero-init on first run, re-zeroed by k_scan3 on every run) ----------
__global__ void k_hist(const int* __restrict__ src, const int* __restrict__ dst) {
    int e = blockIdx.x * blockDim.x + threadIdx.x;
    if (e < EE) {
        atomicAdd(&g_deg_out[src[e]], 1);
        atomicAdd(&g_deg_in[dst[e]], 1);
    }
}

// ---------------- scan of deg_in -> row_ptr, fused norm computation ----------
__global__ void k_scan1() {
    __shared__ int sh[SCAN_B];
    int tid = threadIdx.x;
    int i   = blockIdx.x * SCAN_B + tid;
    int v   = 0;
    if (i < NN) {
        int din  = g_deg_in[i];
        int dout = g_deg_out[i];
        v = din;
        if (din  < 1) din  = 1;
        if (dout < 1) dout = 1;
        g_norm_src[i] = rsqrtf((float)dout);
        g_norm_dst[i] = rsqrtf((float)din);
    }
    sh[tid] = v;
    __syncthreads();
    for (int off = 1; off < SCAN_B; off <<= 1) {
        int t = (tid >= off) ? sh[tid - off] : 0;
        __syncthreads();
        sh[tid] += t;
        __syncthreads();
    }
    int incl = sh[tid];
    if (i < NN) g_row_ptr[i] = incl - v;       // exclusive within block
    if (tid == SCAN_B - 1) g_bsum[blockIdx.x] = incl;
}

__global__ void k_scan2() {
    __shared__ int sh[128];
    int tid = threadIdx.x;
    int v = (tid < NB) ? g_bsum[tid] : 0;
    sh[tid] = v;
    __syncthreads();
    for (int off = 1; off < 128; off <<= 1) {
        int t = (tid >= off) ? sh[tid - off] : 0;
        __syncthreads();
        sh[tid] += t;
        __syncthreads();
    }
    if (tid < NB) g_bsum[tid] = sh[tid] - v;    // exclusive
    if (tid == NB - 1) g_row_ptr[NN] = sh[tid]; // == EE
}

// scan3 + cleanup + layer-1 input prep, all in one pass.
// grid covers NN*16 threads (one float4 of feat each).
__global__ void k_scan3(const float* __restrict__ feat) {
    int j = blockIdx.x * blockDim.x + threadIdx.x;   // float4 index
    if (j < NN) {
        g_row_ptr[j] += g_bsum[j >> 10];
        // deg arrays consumed by k_scan1; fill must be zero before k_fill.
        g_deg_in[j]  = 0;
        g_deg_out[j] = 0;
        g_fill[j]    = 0;
    }
    if (j < NN * 16) {
        int row = j >> 4;
        float ns = g_norm_src[row];
        float4 v = ((const float4*)feat)[j];
        __half2 lo = __floats2half2_rn(v.x * ns, v.y * ns);
        __half2 hi = __floats2half2_rn(v.z * ns, v.w * ns);
        uint2 pk;
        pk.x = *(unsigned int*)&lo;
        pk.y = *(unsigned int*)&hi;
        ((uint2*)g_xn)[j] = pk;
    }
}

// ---------------- CSR fill (grouped by dst) ----------------
__global__ void k_fill(const int* __restrict__ src, const int* __restrict__ dst) {
    int e = blockIdx.x * blockDim.x + threadIdx.x;
    if (e < EE) {
        int d   = dst[e];
        int pos = g_row_ptr[d] + atomicAdd(&g_fill[d], 1);
        g_col[pos] = src[e];
    }
}

// ---------------- aggregation: A[n] = sum_{e: dst=n} xn[src[e]] ----------------
// one warp per node; lane owns 2 cols (half2 = 4B -> 128B line per gather).
__global__ void k_agg() {
    int warp = (blockIdx.x * blockDim.x + threadIdx.x) >> 5;
    int lane = threadIdx.x & 31;
    if (warp >= NN) return;

    int beg = g_row_ptr[warp];
    int end = g_row_ptr[warp + 1];
    const __half2* x2 = (const __half2*)g_xn;

    float2 a0 = make_float2(0.f, 0.f);
    float2 a1 = make_float2(0.f, 0.f);
    float2 a2 = make_float2(0.f, 0.f);
    float2 a3 = make_float2(0.f, 0.f);
    int i = beg;
    for (; i + 3 < end; i += 4) {
        int s0 = __ldg(&g_col[i]);
        int s1 = __ldg(&g_col[i + 1]);
        int s2 = __ldg(&g_col[i + 2]);
        int s3 = __ldg(&g_col[i + 3]);
        float2 v0 = __half22float2(x2[s0 * 32 + lane]);
        float2 v1 = __half22float2(x2[s1 * 32 + lane]);
        float2 v2 = __half22float2(x2[s2 * 32 + lane]);
        float2 v3 = __half22float2(x2[s3 * 32 + lane]);
        a0.x += v0.x; a0.y += v0.y;
        a1.x += v1.x; a1.y += v1.y;
        a2.x += v2.x; a2.y += v2.y;
        a3.x += v3.x; a3.y += v3.y;
    }
    for (; i < end; i++) {
        int s0 = __ldg(&g_col[i]);
        float2 v0 = __half22float2(x2[s0 * 32 + lane]);
        a0.x += v0.x; a0.y += v0.y;
    }
    float sx = (a0.x + a1.x) + (a2.x + a3.x);
    float sy = (a0.y + a1.y) + (a2.y + a3.y);

    ((__half2*)g_A)[warp * 32 + lane] = __floats2half2_rn(sx, sy);
}

// ---------------- tensor-core GEMM + fused epilogue ----------------
// out[n]      = relu((A[n] @ W) * nd[n] + b) + resid[n]        (fp32)
// xn_next[n]  = out[n] * ns[n]                                  (fp16, optional)
// block: 256 threads = 8 warps; warp w handles rows tile*128 + w*16 .. +16.
__global__ void k_gemm_tc(const float* __restrict__ W, const float* __restrict__ bias,
                          const float* __restrict__ resid, float* __restrict__ out,
                          int write_xn) {
    __shared__ __half Ws[DD * DD];           // 8 KB
    __shared__ float  stage[8 * 16 * DD];    // 32 KB
    int tid  = threadIdx.x;
    int wid  = tid >> 5;
    int lane = tid & 31;

    // W fp32 -> fp16 smem (row-major)
    {
        const float4* W4 = (const float4*)W;
        #pragma unroll
        for (int i = tid; i < DD * DD / 4; i += 256) {
            float4 v = W4[i];
            __half2 lo = __floats2half2_rn(v.x, v.y);
            __half2 hi = __floats2half2_rn(v.z, v.w);
            uint2 pk;
            pk.x = *(unsigned int*)&lo;
            pk.y = *(unsigned int*)&hi;
            ((uint2*)Ws)[i] = pk;
        }
    }
    __syncthreads();

    const int n_tiles = (NN + 127) / 128;    // 782
    for (int t = blockIdx.x; t < n_tiles; t += gridDim.x) {
        int rowBase = t * 128 + wid * 16;

        wmma::fragment<wmma::matrix_a, 16, 16, 16, __half, wmma::row_major> a[4];
        #pragma unroll
        for (int k = 0; k < 4; k++)
            wmma::load_matrix_sync(a[k], g_A + (size_t)rowBase * DD + k * 16, DD);

        float* st = &stage[wid * 16 * DD];
        #pragma unroll
        for (int n = 0; n < 4; n++) {
            wmma::fragment<wmma::accumulator, 16, 16, 16, float> acc;
            wmma::fill_fragment(acc, 0.0f);
            #pragma unroll
            for (int k = 0; k < 4; k++) {
                wmma::fragment<wmma::matrix_b, 16, 16, 16, __half, wmma::row_major> bfr;
                wmma::load_matrix_sync(bfr, Ws + (k * 16) * DD + n * 16, DD);
                wmma::mma_sync(acc, a[k], bfr, acc);
            }
            wmma::store_matrix_sync(st + n * 16, acc, DD, wmma::mem_row_major);
        }
        __syncwarp();

        // epilogue: each lane handles 2 cols over 16 rows
        int col = lane * 2;
        #pragma unroll 4
        for (int r = 0; r < 16; r++) {
            int n = rowBase + r;
            if (n < NN) {
                float2 v  = *(float2*)&st[r * DD + col];
                float nd  = g_norm_dst[n];
                float2 bb = ((const float2*)bias)[lane];
                float2 rr = ((const float2*)resid)[n * 32 + lane];  // float2 units
                float2 o;
                o.x = fmaxf(v.x * nd + bb.x, 0.f) + rr.x;
                o.y = fmaxf(v.y * nd + bb.y, 0.f) + rr.y;
                ((float2*)out)[n * 32 + lane] = o;
                if (write_xn) {
                    float ns = g_norm_src[n];
                    ((__half2*)g_xn)[n * 32 + lane] =
                        __floats2half2_rn(o.x * ns, o.y * ns);
                }
            }
        }
        __syncwarp();   // stage reuse safety across tile iterations
    }
}

// ---------------- launch ----------------
extern "C" void kernel_launch(void* const* d_in, const int* in_sizes, int n_in,
                              void* d_out, int out_size) {
    const float* feat = (const float*)d_in[0];
    const int*   src  = (const int*)d_in[1];
    const int*   dst  = (const int*)d_in[2];
    // d_in[3] = etype (unused)
    const float* w1 = (const float*)d_in[4];
    const float* b1 = (const float*)d_in[5];
    const float* w2 = (const float*)d_in[6];
    const float* b2 = (const float*)d_in[7];
    const float* w3 = (const float*)d_in[8];
    const float* b3 = (const float*)d_in[9];
    float* out = (float*)d_out;

    void *pa = nullptr, *pb = nullptr;
    cudaGetSymbolAddress(&pa, g_bufA);
    cudaGetSymbolAddress(&pb, g_bufB);
    float* bufA = (float*)pa;
    float* bufB = (float*)pb;

    const int gE    = (EE + 255) / 256;
    const int gAgg  = (NN * 32 + 255) / 256;
    const int gCvt  = (NN * 16 + 255) / 256;
    const int gGemm = (NN + 127) / 128;

    // graph structure (deg/fill arrays zero on entry; re-zeroed inside k_scan3)
    k_hist<<<gE, 256>>>(src, dst);
    k_scan1<<<NB, SCAN_B>>>();
    k_scan2<<<1, 128>>>();
    k_scan3<<<gCvt, 256>>>(feat);
    k_fill<<<gE, 256>>>(src, dst);

    // layer 1
    k_agg<<<gAgg, 256>>>();
    k_gemm_tc<<<gGemm, 256>>>(w1, b1, feat, bufA, 1);
    // layer 2
    k_agg<<<gAgg, 256>>>();
    k_gemm_tc<<<gGemm, 256>>>(w2, b2, bufA, bufB, 1);
    // layer 3
    k_agg<<<gAgg, 256>>>();
    k_gemm_tc<<<gGemm, 256>>>(w3, b3, bufB, out, 0);
}